// round 9
// baseline (speedup 1.0000x reference)
#include <cuda_runtime.h>
#include <cuda_fp16.h>
#include <math.h>
#include <stdint.h>

#define NN 50000
#define EE 300000
#define DD 256
#define FF 1024
#define CC 40

// ---------------- scratch (device globals) ----------------
__device__ float g_norms[NN];
__device__ float g_normd[NN];
__device__ int   g_odeg[NN];
__device__ int   g_ideg[NN];
__device__ int   g_offs[NN + 1];
__device__ int   g_cursor[NN];
__device__ int   g_bsum[256];
__device__ int   g_esrc[EE];
__device__ __half g_HA[(size_t)NN * DD];   // fp16 activations
__device__ __half g_HB[(size_t)NN * DD];   // fp16 spmm output
__device__ float g_psum[512 * DD];         // bn partial sums (per GEMM block)
__device__ float g_psq[512 * DD];
__device__ float g_scale[DD];
__device__ float g_shift[DD];
// fp16 transposed weights: WT_fc [256][1024], WT1/2/3 [256][256]
__device__ __half g_WT[(size_t)DD * FF + 3 * (size_t)DD * DD];

// ---------------- helpers ----------------
__device__ __forceinline__ uint32_t smem_u32(const void* p) {
    uint32_t a;
    asm("{ .reg .u64 t; cvta.to.shared.u64 t, %1; cvt.u32.u64 %0, t; }" : "=r"(a) : "l"(p));
    return a;
}
__device__ __forceinline__ uint32_t f22h(float a, float b) {
    __half2 h = __float22half2_rn(make_float2(a, b));
    return *(uint32_t*)&h;
}
__device__ __forceinline__ void ldsm4(uint32_t* r, uint32_t addr) {
    asm volatile("ldmatrix.sync.aligned.m8n8.x4.shared.b16 {%0,%1,%2,%3}, [%4];"
                 : "=r"(r[0]), "=r"(r[1]), "=r"(r[2]), "=r"(r[3]) : "r"(addr));
}
__device__ __forceinline__ void mma16816(float* c, const uint32_t* a, const uint32_t* b) {
    asm volatile(
        "mma.sync.aligned.m16n8k16.row.col.f32.f16.f16.f32 "
        "{%0,%1,%2,%3}, {%4,%5,%6,%7}, {%8,%9}, {%0,%1,%2,%3};"
        : "+f"(c[0]), "+f"(c[1]), "+f"(c[2]), "+f"(c[3])
        : "r"(a[0]), "r"(a[1]), "r"(a[2]), "r"(a[3]), "r"(b[0]), "r"(b[1]));
}
__device__ __forceinline__ void cp16(uint32_t dst, const void* src) {
    asm volatile("cp.async.cg.shared.global [%0], [%1], 16;" :: "r"(dst), "l"(src));
}
__device__ __forceinline__ void cp16z(uint32_t dst, const void* src, bool valid) {
    int sz = valid ? 16 : 0;
    asm volatile("cp.async.cg.shared.global [%0], [%1], 16, %2;"
                 :: "r"(dst), "l"(src), "r"(sz));
}
#define CP_COMMIT() asm volatile("cp.async.commit_group;" ::: "memory")
#define CP_WAIT0()  asm volatile("cp.async.wait_group 0;" ::: "memory")

// swizzled half offset within a [rows][32] half tile (64B rows, 4x16B groups)
__device__ __forceinline__ int swoff(int r, int c) {
    return r * 32 + ((((c >> 3) ^ ((r >> 1) & 3)) << 3)) + (c & 7);
}

// ---------------- degree + norm ----------------
__global__ void deg_kernel(const int* __restrict__ src, const int* __restrict__ dst,
                           int* __restrict__ od, int* __restrict__ id, int E) {
    int t = blockIdx.x * blockDim.x + threadIdx.x;
    if (t >= E) return;
    atomicAdd(&od[src[t]], 1);
    atomicAdd(&id[dst[t]], 1);
}

__global__ void norm_kernel(const int* __restrict__ od, const int* __restrict__ id,
                            float* __restrict__ ns, float* __restrict__ nd, int n) {
    int t = blockIdx.x * blockDim.x + threadIdx.x;
    if (t >= n) return;
    ns[t] = rsqrtf(fmaxf((float)od[t], 1.0f));
    nd[t] = rsqrtf(fmaxf((float)id[t], 1.0f));
}

// ---------------- CSR build: 3-phase multi-block scan ----------------
#define SCB 256
__global__ void scan_part(const int* __restrict__ deg, int* __restrict__ bsum, int n) {
    __shared__ int sh[SCB];
    int t = threadIdx.x;
    int i = blockIdx.x * SCB + t;
    sh[t] = (i < n) ? deg[i] : 0;
    __syncthreads();
#pragma unroll
    for (int o = 128; o > 0; o >>= 1) {
        if (t < o) sh[t] += sh[t + o];
        __syncthreads();
    }
    if (t == 0) bsum[blockIdx.x] = sh[0];
}

__global__ void scan_base(int* __restrict__ bsum, int nb) {
    __shared__ int sh[256];
    int t = threadIdx.x;
    int v = (t < nb) ? bsum[t] : 0;
    sh[t] = v;
    __syncthreads();
#pragma unroll
    for (int o = 1; o < 256; o <<= 1) {
        int u = (t >= o) ? sh[t - o] : 0;
        __syncthreads();
        sh[t] += u;
        __syncthreads();
    }
    if (t < nb) bsum[t] = sh[t] - v;   // exclusive
}

__global__ void scan_final(const int* __restrict__ deg, const int* __restrict__ bsum,
                           int* __restrict__ offs, int* __restrict__ cursor, int n) {
    __shared__ int sh[SCB];
    int t = threadIdx.x;
    int i = blockIdx.x * SCB + t;
    int v = (i < n) ? deg[i] : 0;
    sh[t] = v;
    __syncthreads();
#pragma unroll
    for (int o = 1; o < SCB; o <<= 1) {
        int u = (t >= o) ? sh[t - o] : 0;
        __syncthreads();
        sh[t] += u;
        __syncthreads();
    }
    int excl = sh[t] - v + bsum[blockIdx.x];
    if (i < n) {
        offs[i] = excl;
        cursor[i] = excl;
        if (i == n - 1) offs[n] = excl + v;
    }
}

__global__ void fill_kernel(const int* __restrict__ src, const int* __restrict__ dst,
                            int* __restrict__ cursor, int* __restrict__ esrc, int E) {
    int e = blockIdx.x * blockDim.x + threadIdx.x;
    if (e >= E) return;
    int p = atomicAdd(&cursor[dst[e]], 1);
    esrc[p] = src[e];
}

// ---------------- SpMM gather (fp16 in/out, fp32 accum, norm_d folded in) ----------------
__global__ __launch_bounds__(256) void spmm_gather_h(
    const __half* __restrict__ X, const int* __restrict__ esrc,
    const int* __restrict__ offs, const float* __restrict__ ns,
    const float* __restrict__ nd, __half* __restrict__ Out, int n)
{
    int row = blockIdx.x * 8 + (threadIdx.x >> 5);
    int lane = threadIdx.x & 31;
    if (row >= n) return;
    int o0 = offs[row], o1 = offs[row + 1];
    float acc[8];
#pragma unroll
    for (int k = 0; k < 8; k++) acc[k] = 0.f;

    int i = o0;
    for (; i + 4 <= o1; i += 4) {
        int s[4];
        float c[4];
        uint4 u[4];
#pragma unroll
        for (int j = 0; j < 4; j++) s[j] = __ldg(&esrc[i + j]);
#pragma unroll
        for (int j = 0; j < 4; j++) {
            c[j] = __ldg(&ns[s[j]]);
            u[j] = *(const uint4*)&X[(size_t)s[j] * DD + lane * 8];
        }
#pragma unroll
        for (int j = 0; j < 4; j++) {
            const __half2* h = (const __half2*)&u[j];
#pragma unroll
            for (int k = 0; k < 4; k++) {
                float2 v = __half22float2(h[k]);
                acc[2 * k] += v.x * c[j];
                acc[2 * k + 1] += v.y * c[j];
            }
        }
    }
    for (; i < o1; i++) {
        int s = __ldg(&esrc[i]);
        float c = __ldg(&ns[s]);
        uint4 u = *(const uint4*)&X[(size_t)s * DD + lane * 8];
        const __half2* h = (const __half2*)&u;
#pragma unroll
        for (int k = 0; k < 4; k++) {
            float2 v = __half22float2(h[k]);
            acc[2 * k] += v.x * c;
            acc[2 * k + 1] += v.y * c;
        }
    }
    float d = __ldg(&nd[row]);
    uint4 o;
    uint32_t* ow = (uint32_t*)&o;
#pragma unroll
    for (int k = 0; k < 4; k++)
        ow[k] = f22h(acc[2 * k] * d, acc[2 * k + 1] * d);
    *(uint4*)&Out[(size_t)row * DD + lane * 8] = o;
}

// ---------------- fused weight transpose (fp32 -> fp16 transposed, all 4 mats) ----------------
__global__ void transpose_all(const float* __restrict__ W_fc, const float* __restrict__ W1,
                              const float* __restrict__ W2, const float* __restrict__ W3,
                              __half* __restrict__ WT, int F, int D)
{
    int z = blockIdx.z;
    const float* W;
    __half* Wt;
    int K;
    if (z == 0) { W = W_fc; Wt = WT; K = F; }
    else {
        K = D;
        W = (z == 1) ? W1 : (z == 2) ? W2 : W3;
        Wt = WT + (size_t)D * F + (size_t)(z - 1) * D * D;
    }
    int bx = blockIdx.x * 32;  // K dim
    if (bx >= K) return;
    int by = blockIdx.y * 32;  // N dim
    __shared__ float t[32][33];
    int x = threadIdx.x, y = threadIdx.y;
    for (int j = 0; j < 32; j += 8)
        t[y + j][x] = W[(size_t)(bx + y + j) * D + by + x];
    __syncthreads();
    for (int j = 0; j < 32; j += 8)
        Wt[(size_t)(by + y + j) * K + bx + x] = __float2half_rn(t[x][y + j]);
}

// ---------------- fp16 mma GEMM, 128x256 tile, cp.async pipeline ----------------
// C[M,256] = A[M,K] @ W + bias; Bt = fp16 W^T [256][K]. Nn fixed = 256.
// 256 threads, 8 warps, warp tile 64x64, acc[4][8][4]; grid (1, ceil(M/128)).
// STATS: also emit per-block column sum/sumsq of fp32 (acc+bias) into psum/psq.
template <bool A_HALF, bool OUT_HALF, bool STATS>
__global__ __launch_bounds__(256, 1) void mma_gemm_t(
    const void* __restrict__ Ap, const __half* __restrict__ Bt,
    const float* __restrict__ bias, void* __restrict__ Cp,
    float* __restrict__ psum, float* __restrict__ psq,
    int M, int K)
{
    __shared__ __align__(16) __half As[2][128 * 32];
    __shared__ __align__(16) __half Bs[2][256 * 32];

    const int tid = threadIdx.x;
    const int lane = tid & 31;
    const int warp = tid >> 5;
    const int wm = warp & 1;    // 64-row half
    const int wn = warp >> 1;   // 64-col quarter
    const int brow = blockIdx.y * 128;
    const int l8 = lane & 7;
    const int q = lane >> 3;

    const float* Af = (const float*)Ap;
    const __half* Ah = (const __half*)Ap;

    const uint32_t asb = smem_u32(&As[0][0]);
    const uint32_t bsb = smem_u32(&Bs[0][0]);

    float acc[4][8][4];
#pragma unroll
    for (int i = 0; i < 4; i++)
#pragma unroll
        for (int j = 0; j < 8; j++)
#pragma unroll
            for (int l = 0; l < 4; l++) acc[i][j][l] = 0.f;

    // load mappings
    int fR[4], fC[4];   // fp32 A: 4 x float4
#pragma unroll
    for (int i = 0; i < 4; i++) {
        int idx = tid + i * 256;
        fR[i] = idx >> 3;
        fC[i] = (idx & 7) << 2;
    }
    int hR[2], hC[2];   // fp16 A: 2 x uint4 (cp.async)
#pragma unroll
    for (int i = 0; i < 2; i++) {
        int idx = tid + i * 256;
        hR[i] = idx >> 2;
        hC[i] = (idx & 3) << 3;
    }
    int bR[4], bC[4];   // B: 4 x uint4 over 256 rows (cp.async)
#pragma unroll
    for (int i = 0; i < 4; i++) {
        int idx = tid + i * 256;
        bR[i] = idx >> 2;
        bC[i] = (idx & 3) << 3;
    }

    const int nch = K >> 5;
    float4 ra[4];

    // ---- prologue: chunk 0
    if (A_HALF) {
#pragma unroll
        for (int i = 0; i < 2; i++) {
            int gr = brow + hR[i];
            cp16z(asb + swoff(hR[i], hC[i]) * 2, &Ah[(size_t)gr * K + hC[i]], gr < M);
        }
    } else {
#pragma unroll
        for (int i = 0; i < 4; i++) {
            int gr = brow + fR[i];
            ra[i] = (gr < M) ? *(const float4*)&Af[(size_t)gr * K + fC[i]]
                             : make_float4(0.f, 0.f, 0.f, 0.f);
        }
#pragma unroll
        for (int i = 0; i < 4; i++)
            *(uint2*)&As[0][swoff(fR[i], fC[i])] =
                make_uint2(f22h(ra[i].x, ra[i].y), f22h(ra[i].z, ra[i].w));
    }
#pragma unroll
    for (int i = 0; i < 4; i++)
        cp16(bsb + swoff(bR[i], bC[i]) * 2, &Bt[(size_t)bR[i] * K + bC[i]]);
    CP_COMMIT();
    CP_WAIT0();
    __syncthreads();

    for (int c = 0; c < nch; c++) {
        const int buf = c & 1;
        const int nb = buf ^ 1;
        const bool more = (c + 1 < nch);
        if (more) {
            int k0 = (c + 1) << 5;
            if (A_HALF) {
#pragma unroll
                for (int i = 0; i < 2; i++) {
                    int gr = brow + hR[i];
                    cp16z(asb + (nb * 4096 + swoff(hR[i], hC[i])) * 2,
                          &Ah[(size_t)gr * K + k0 + hC[i]], gr < M);
                }
            } else {
#pragma unroll
                for (int i = 0; i < 4; i++) {
                    int gr = brow + fR[i];
                    ra[i] = (gr < M) ? *(const float4*)&Af[(size_t)gr * K + k0 + fC[i]]
                                     : make_float4(0.f, 0.f, 0.f, 0.f);
                }
            }
#pragma unroll
            for (int i = 0; i < 4; i++)
                cp16(bsb + (nb * 8192 + swoff(bR[i], bC[i])) * 2,
                     &Bt[(size_t)bR[i] * K + k0 + bC[i]]);
            CP_COMMIT();
        }

        // mma over smem[buf]: two k16 halves
#pragma unroll
        for (int kk = 0; kk < 2; kk++) {
            uint32_t af[4][4], bf[8][2];
#pragma unroll
            for (int mi = 0; mi < 4; mi++) {
                int row = wm * 64 + mi * 16 + ((q & 1) << 3) + l8;
                int col = kk * 16 + ((q >> 1) << 3);
                ldsm4(af[mi], smem_u32(&As[buf][swoff(row, col)]));
            }
#pragma unroll
            for (int p = 0; p < 4; p++) {
                int row = wn * 64 + p * 16 + ((q >> 1) << 3) + l8;
                int col = kk * 16 + ((q & 1) << 3);
                uint32_t r4[4];
                ldsm4(r4, smem_u32(&Bs[buf][swoff(row, col)]));
                bf[2 * p][0] = r4[0]; bf[2 * p][1] = r4[1];
                bf[2 * p + 1][0] = r4[2]; bf[2 * p + 1][1] = r4[3];
            }
#pragma unroll
            for (int mi = 0; mi < 4; mi++)
#pragma unroll
                for (int ni = 0; ni < 8; ni++)
                    mma16816(acc[mi][ni], af[mi], bf[ni]);
        }

        if (more) {
            if (!A_HALF) {
#pragma unroll
                for (int i = 0; i < 4; i++)
                    *(uint2*)&As[nb][swoff(fR[i], fC[i])] =
                        make_uint2(f22h(ra[i].x, ra[i].y), f22h(ra[i].z, ra[i].w));
            }
            CP_WAIT0();
        }
        __syncthreads();
    }

    // ---- epilogue: write C
    float* Cf = (float*)Cp;
    __half* Ch = (__half*)Cp;
#pragma unroll
    for (int mi = 0; mi < 4; mi++) {
        int r0 = brow + wm * 64 + mi * 16 + (lane >> 2);
#pragma unroll
        for (int ni = 0; ni < 8; ni++) {
            int cc = wn * 64 + ni * 8 + (lane & 3) * 2;
            float b0 = bias[cc], b1 = bias[cc + 1];
            if (r0 < M) {
                float v0 = acc[mi][ni][0] + b0, v1 = acc[mi][ni][1] + b1;
                if (OUT_HALF) *(uint32_t*)&Ch[(size_t)r0 * 256 + cc] = f22h(v0, v1);
                else *(float2*)&Cf[(size_t)r0 * 256 + cc] = make_float2(v0, v1);
            }
            if (r0 + 8 < M) {
                float v0 = acc[mi][ni][2] + b0, v1 = acc[mi][ni][3] + b1;
                if (OUT_HALF) *(uint32_t*)&Ch[(size_t)(r0 + 8) * 256 + cc] = f22h(v0, v1);
                else *(float2*)&Cf[(size_t)(r0 + 8) * 256 + cc] = make_float2(v0, v1);
            }
        }
    }

    // ---- fused BN stats: per-block column sum / sumsq
    if (STATS) {
        float* ssum = (float*)&As[0][0];   // 256 floats
        float* ssq = ssum + 256;           // 256 floats
        ssum[tid] = 0.f;
        ssq[tid] = 0.f;
        __syncthreads();
#pragma unroll
        for (int ni = 0; ni < 8; ni++) {
#pragma unroll
            for (int j = 0; j < 2; j++) {
                int cc = wn * 64 + ni * 8 + (lane & 3) * 2 + j;
                float b = bias[cc];
                float s = 0.f, qv = 0.f;
#pragma unroll
                for (int mi = 0; mi < 4; mi++) {
                    int r0 = brow + wm * 64 + mi * 16 + (lane >> 2);
                    if (r0 < M) {
                        float v = acc[mi][ni][j] + b;
                        s += v; qv += v * v;
                    }
                    if (r0 + 8 < M) {
                        float v = acc[mi][ni][2 + j] + b;
                        s += v; qv += v * v;
                    }
                }
                atomicAdd(&ssum[cc], s);
                atomicAdd(&ssq[cc], qv);
            }
        }
        __syncthreads();
        psum[blockIdx.y * DD + tid] = ssum[tid];
        psq[blockIdx.y * DD + tid] = ssq[tid];
    }
}

// ---------------- batchnorm finalize + apply ----------------
__global__ void bn_finalize_kernel(const float* __restrict__ psum, const float* __restrict__ psq,
                                   const float* __restrict__ gamma, const float* __restrict__ beta,
                                   float* __restrict__ scale, float* __restrict__ shift,
                                   int nparts, int Nrows)
{
    int c = threadIdx.x;
    float s = 0.f, q = 0.f;
    for (int r = 0; r < nparts; r++) {
        s += psum[r * DD + c];
        q += psq[r * DD + c];
    }
    float invn = 1.0f / (float)Nrows;
    float mu = s * invn;
    float var = q * invn - mu * mu;
    float inv = rsqrtf(var + 1e-5f);
    float sc = gamma[c] * inv;
    scale[c] = sc;
    shift[c] = beta[c] - mu * sc;
}

__global__ void bn_apply_elu_h(__half* __restrict__ X, const float* __restrict__ scale,
                               const float* __restrict__ shift, long total2)
{
    long t = (long)blockIdx.x * blockDim.x + threadIdx.x;
    if (t >= total2) return;
    int col2 = (int)(t & (DD / 2 - 1));
    __half2* X2 = (__half2*)X;
    float2 v = __half22float2(X2[t]);
    float y0 = v.x * scale[col2 * 2] + shift[col2 * 2];
    float y1 = v.y * scale[col2 * 2 + 1] + shift[col2 * 2 + 1];
    y0 = (y0 > 0.f) ? y0 : expm1f(y0);
    y1 = (y1 > 0.f) ? y1 : expm1f(y1);
    X2[t] = __floats2half2_rn(y0, y1);
}

// ---------------- classifier head ----------------
#define HEAD_ROWS 8
__global__ __launch_bounds__(CC * HEAD_ROWS) void logits_kernel(
    const float* __restrict__ X, const float* __restrict__ W,
    const float* __restrict__ b, float* __restrict__ Out, int Nrows)
{
    __shared__ float Ws[DD * CC];
    for (int i = threadIdx.x; i < DD * CC; i += blockDim.x) Ws[i] = W[i];
    __syncthreads();
    int c = threadIdx.x % CC;
    int rloc = threadIdx.x / CC;
    int row = blockIdx.x * HEAD_ROWS + rloc;
    if (row >= Nrows) return;
    const float* a = &X[(size_t)row * DD];
    float acc = b[c];
#pragma unroll 8
    for (int k = 0; k < DD; k += 4) {
        float4 av = *(const float4*)&a[k];
        acc += av.x * Ws[(k + 0) * CC + c];
        acc += av.y * Ws[(k + 1) * CC + c];
        acc += av.z * Ws[(k + 2) * CC + c];
        acc += av.w * Ws[(k + 3) * CC + c];
    }
    Out[(size_t)row * CC + c] = acc;
}

// ---------------- driver ----------------
extern "C" void kernel_launch(void* const* d_in, const int* in_sizes, int n_in,
                              void* d_out, int out_size)
{
    const float* feat  = (const float*)d_in[0];
    const int*   src   = (const int*)d_in[1];
    const int*   dst   = (const int*)d_in[2];
    const float* W_fc  = (const float*)d_in[3];
    const float* b_fc  = (const float*)d_in[4];
    const float* W1    = (const float*)d_in[5];
    const float* b1    = (const float*)d_in[6];
    const float* W2    = (const float*)d_in[7];
    const float* b2    = (const float*)d_in[8];
    const float* W3    = (const float*)d_in[9];
    const float* b3    = (const float*)d_in[10];
    const float* gamma = (const float*)d_in[11];
    const float* beta  = (const float*)d_in[12];
    const float* W_lin = (const float*)d_in[13];
    const float* b_lin = (const float*)d_in[14];

    const int D = in_sizes[4];             // 256
    const int F = in_sizes[3] / D;         // 1024
    const int N = in_sizes[0] / F;         // 50000
    const int E = in_sizes[1];             // 300000

    float *p_norms, *p_normd, *p_psum, *p_psq, *p_scale, *p_shift;
    int *p_odeg, *p_ideg, *p_offs, *p_cursor, *p_bsum, *p_esrc;
    __half *p_HA, *p_HB, *p_WT;
    cudaGetSymbolAddress((void**)&p_norms, g_norms);
    cudaGetSymbolAddress((void**)&p_normd, g_normd);
    cudaGetSymbolAddress((void**)&p_odeg, g_odeg);
    cudaGetSymbolAddress((void**)&p_ideg, g_ideg);
    cudaGetSymbolAddress((void**)&p_offs, g_offs);
    cudaGetSymbolAddress((void**)&p_cursor, g_cursor);
    cudaGetSymbolAddress((void**)&p_bsum, g_bsum);
    cudaGetSymbolAddress((void**)&p_esrc, g_esrc);
    cudaGetSymbolAddress((void**)&p_HA, g_HA);
    cudaGetSymbolAddress((void**)&p_HB, g_HB);
    cudaGetSymbolAddress((void**)&p_psum, g_psum);
    cudaGetSymbolAddress((void**)&p_psq, g_psq);
    cudaGetSymbolAddress((void**)&p_scale, g_scale);
    cudaGetSymbolAddress((void**)&p_shift, g_shift);
    cudaGetSymbolAddress((void**)&p_WT, g_WT);

    // one-time stream/event setup
    static cudaStream_t s2 = nullptr;
    static cudaEvent_t evFork = nullptr, evJoin = nullptr;
    if (!s2) {
        cudaStreamCreateWithFlags(&s2, cudaStreamNonBlocking);
        cudaEventCreateWithFlags(&evFork, cudaEventDisableTiming);
        cudaEventCreateWithFlags(&evJoin, cudaEventDisableTiming);
    }

    float* out_x = (float*)d_out;                       // [N, D]
    float* out_logits = (float*)d_out + (size_t)N * D;  // [N, C]

    __half* WT_fc = p_WT;
    __half* WT1 = p_WT + (size_t)D * F;
    __half* WT2 = WT1 + (size_t)D * D;
    __half* WT3 = WT2 + (size_t)D * D;

    const int nsb = (N + SCB - 1) / SCB;
    const int mblocks = (N + 127) / 128;

    // ---- fork: CSR/degree chain on s2, overlapped with transpose + FC GEMM
    cudaEventRecord(evFork, 0);
    cudaStreamWaitEvent(s2, evFork, 0);

    cudaMemsetAsync(p_odeg, 0, N * sizeof(int), s2);
    cudaMemsetAsync(p_ideg, 0, N * sizeof(int), s2);
    deg_kernel<<<(E + 255) / 256, 256, 0, s2>>>(src, dst, p_odeg, p_ideg, E);
    norm_kernel<<<(N + 255) / 256, 256, 0, s2>>>(p_odeg, p_ideg, p_norms, p_normd, N);
    scan_part<<<nsb, SCB, 0, s2>>>(p_ideg, p_bsum, N);
    scan_base<<<1, 256, 0, s2>>>(p_bsum, nsb);
    scan_final<<<nsb, SCB, 0, s2>>>(p_ideg, p_bsum, p_offs, p_cursor, N);
    fill_kernel<<<(E + 255) / 256, 256, 0, s2>>>(src, dst, p_cursor, p_esrc, E);
    cudaEventRecord(evJoin, s2);

    // ---- main stream: weights + FC GEMM
    {
        dim3 blk(32, 8);
        dim3 grid(F / 32, D / 32, 4);
        transpose_all<<<grid, blk>>>(W_fc, W1, W2, W3, p_WT, F, D);
    }
    dim3 ggrid(1, mblocks);
    mma_gemm_t<false, true, false><<<ggrid, 256>>>(feat, WT_fc, b_fc, p_HA,
                                                   nullptr, nullptr, N, F);

    // ---- join before first spmm
    cudaStreamWaitEvent(0, evJoin, 0);

    const __half* WTs[3] = {WT1, WT2, WT3};
    const float* bs[3] = {b1, b2, b3};
    long total2 = (long)N * D / 2;

    for (int l = 0; l < 3; l++) {
        spmm_gather_h<<<(N + 7) / 8, 256>>>(p_HA, p_esrc, p_offs, p_norms, p_normd, p_HB, N);
        if (l < 2) {
            mma_gemm_t<true, true, true><<<ggrid, 256>>>(p_HB, WTs[l], bs[l], p_HA,
                                                         p_psum, p_psq, N, D);
            bn_finalize_kernel<<<1, D>>>(p_psum, p_psq, gamma, beta, p_scale, p_shift,
                                         mblocks, N);
            bn_apply_elu_h<<<(int)((total2 + 255) / 256), 256>>>(p_HA, p_scale, p_shift, total2);
        } else {
            mma_gemm_t<true, false, false><<<ggrid, 256>>>(p_HB, WTs[l], bs[l], out_x,
                                                           nullptr, nullptr, N, D);
        }
    }

    // 3. logits
    logits_kernel<<<(N + HEAD_ROWS - 1) / HEAD_ROWS, CC * HEAD_ROWS>>>(
        out_x, W_lin, b_lin, out_logits, N);
}

// round 10
// speedup vs baseline: 1.1436x; 1.1436x over previous
#include <cuda_runtime.h>
#include <cuda_fp16.h>
#include <math.h>
#include <stdint.h>

#define NN 50000
#define EE 300000
#define DD 256
#define FF 1024
#define CC 40

// ---------------- scratch (device globals) ----------------
__device__ float g_norms[NN];
__device__ float g_normd[NN];
__device__ int   g_odeg[NN];
__device__ int   g_ideg[NN];
__device__ int   g_offs[NN + 1];
__device__ int   g_cursor[NN];
__device__ int   g_bsum[256];
__device__ int   g_esrc[EE];
__device__ __half g_HA[(size_t)NN * DD];   // fp16 activations
__device__ __half g_HB[(size_t)NN * DD];   // fp16 spmm output
__device__ float g_psum[512 * DD];         // bn partial sums
__device__ float g_psq[512 * DD];
__device__ float g_scale[DD];
__device__ float g_shift[DD];
// fp16 transposed weights: WT_fc [256][1024], WT1/2/3 [256][256]
__device__ __half g_WT[(size_t)DD * FF + 3 * (size_t)DD * DD];

// ---------------- helpers ----------------
__device__ __forceinline__ uint32_t smem_u32(const void* p) {
    uint32_t a;
    asm("{ .reg .u64 t; cvta.to.shared.u64 t, %1; cvt.u32.u64 %0, t; }" : "=r"(a) : "l"(p));
    return a;
}
__device__ __forceinline__ uint32_t f22h(float a, float b) {
    __half2 h = __float22half2_rn(make_float2(a, b));
    return *(uint32_t*)&h;
}
__device__ __forceinline__ void ldsm4(uint32_t* r, uint32_t addr) {
    asm volatile("ldmatrix.sync.aligned.m8n8.x4.shared.b16 {%0,%1,%2,%3}, [%4];"
                 : "=r"(r[0]), "=r"(r[1]), "=r"(r[2]), "=r"(r[3]) : "r"(addr));
}
__device__ __forceinline__ void mma16816(float* c, const uint32_t* a, const uint32_t* b) {
    asm volatile(
        "mma.sync.aligned.m16n8k16.row.col.f32.f16.f16.f32 "
        "{%0,%1,%2,%3}, {%4,%5,%6,%7}, {%8,%9}, {%0,%1,%2,%3};"
        : "+f"(c[0]), "+f"(c[1]), "+f"(c[2]), "+f"(c[3])
        : "r"(a[0]), "r"(a[1]), "r"(a[2]), "r"(a[3]), "r"(b[0]), "r"(b[1]));
}
__device__ __forceinline__ void cp16(uint32_t dst, const void* src) {
    asm volatile("cp.async.cg.shared.global [%0], [%1], 16;" :: "r"(dst), "l"(src));
}
__device__ __forceinline__ void cp16z(uint32_t dst, const void* src, bool valid) {
    int sz = valid ? 16 : 0;
    asm volatile("cp.async.cg.shared.global [%0], [%1], 16, %2;"
                 :: "r"(dst), "l"(src), "r"(sz));
}
#define CP_COMMIT() asm volatile("cp.async.commit_group;" ::: "memory")
#define CP_WAIT0()  asm volatile("cp.async.wait_group 0;" ::: "memory")

// swizzled half offset within a [rows][32] half tile (64B rows, 4x16B groups)
__device__ __forceinline__ int swoff(int r, int c) {
    return r * 32 + ((((c >> 3) ^ ((r >> 1) & 3)) << 3)) + (c & 7);
}

// ---------------- degree + norm ----------------
__global__ void deg_kernel(const int* __restrict__ src, const int* __restrict__ dst,
                           int* __restrict__ od, int* __restrict__ id, int E) {
    int t = blockIdx.x * blockDim.x + threadIdx.x;
    if (t >= E) return;
    atomicAdd(&od[src[t]], 1);
    atomicAdd(&id[dst[t]], 1);
}

__global__ void norm_kernel(const int* __restrict__ od, const int* __restrict__ id,
                            float* __restrict__ ns, float* __restrict__ nd, int n) {
    int t = blockIdx.x * blockDim.x + threadIdx.x;
    if (t >= n) return;
    ns[t] = rsqrtf(fmaxf((float)od[t], 1.0f));
    nd[t] = rsqrtf(fmaxf((float)id[t], 1.0f));
}

// ---------------- CSR build: 3-phase multi-block scan ----------------
#define SCB 256
__global__ void scan_part(const int* __restrict__ deg, int* __restrict__ bsum, int n) {
    __shared__ int sh[SCB];
    int t = threadIdx.x;
    int i = blockIdx.x * SCB + t;
    sh[t] = (i < n) ? deg[i] : 0;
    __syncthreads();
#pragma unroll
    for (int o = 128; o > 0; o >>= 1) {
        if (t < o) sh[t] += sh[t + o];
        __syncthreads();
    }
    if (t == 0) bsum[blockIdx.x] = sh[0];
}

__global__ void scan_base(int* __restrict__ bsum, int nb) {
    __shared__ int sh[256];
    int t = threadIdx.x;
    int v = (t < nb) ? bsum[t] : 0;
    sh[t] = v;
    __syncthreads();
#pragma unroll
    for (int o = 1; o < 256; o <<= 1) {
        int u = (t >= o) ? sh[t - o] : 0;
        __syncthreads();
        sh[t] += u;
        __syncthreads();
    }
    if (t < nb) bsum[t] = sh[t] - v;   // exclusive
}

__global__ void scan_final(const int* __restrict__ deg, const int* __restrict__ bsum,
                           int* __restrict__ offs, int* __restrict__ cursor, int n) {
    __shared__ int sh[SCB];
    int t = threadIdx.x;
    int i = blockIdx.x * SCB + t;
    int v = (i < n) ? deg[i] : 0;
    sh[t] = v;
    __syncthreads();
#pragma unroll
    for (int o = 1; o < SCB; o <<= 1) {
        int u = (t >= o) ? sh[t - o] : 0;
        __syncthreads();
        sh[t] += u;
        __syncthreads();
    }
    int excl = sh[t] - v + bsum[blockIdx.x];
    if (i < n) {
        offs[i] = excl;
        cursor[i] = excl;
        if (i == n - 1) offs[n] = excl + v;
    }
}

__global__ void fill_kernel(const int* __restrict__ src, const int* __restrict__ dst,
                            int* __restrict__ cursor, int* __restrict__ esrc, int E) {
    int e = blockIdx.x * blockDim.x + threadIdx.x;
    if (e >= E) return;
    int p = atomicAdd(&cursor[dst[e]], 1);
    esrc[p] = src[e];
}

// ---------------- SpMM gather (fp16 in/out, fp32 accum, norm_d folded in) ----------------
__global__ __launch_bounds__(256) void spmm_gather_h(
    const __half* __restrict__ X, const int* __restrict__ esrc,
    const int* __restrict__ offs, const float* __restrict__ ns,
    const float* __restrict__ nd, __half* __restrict__ Out, int n)
{
    int row = blockIdx.x * 8 + (threadIdx.x >> 5);
    int lane = threadIdx.x & 31;
    if (row >= n) return;
    int o0 = offs[row], o1 = offs[row + 1];
    float acc[8];
#pragma unroll
    for (int k = 0; k < 8; k++) acc[k] = 0.f;

    int i = o0;
    for (; i + 4 <= o1; i += 4) {
        int s[4];
        float c[4];
        uint4 u[4];
#pragma unroll
        for (int j = 0; j < 4; j++) s[j] = __ldg(&esrc[i + j]);
#pragma unroll
        for (int j = 0; j < 4; j++) {
            c[j] = __ldg(&ns[s[j]]);
            u[j] = *(const uint4*)&X[(size_t)s[j] * DD + lane * 8];
        }
#pragma unroll
        for (int j = 0; j < 4; j++) {
            const __half2* h = (const __half2*)&u[j];
#pragma unroll
            for (int k = 0; k < 4; k++) {
                float2 v = __half22float2(h[k]);
                acc[2 * k] += v.x * c[j];
                acc[2 * k + 1] += v.y * c[j];
            }
        }
    }
    for (; i < o1; i++) {
        int s = __ldg(&esrc[i]);
        float c = __ldg(&ns[s]);
        uint4 u = *(const uint4*)&X[(size_t)s * DD + lane * 8];
        const __half2* h = (const __half2*)&u;
#pragma unroll
        for (int k = 0; k < 4; k++) {
            float2 v = __half22float2(h[k]);
            acc[2 * k] += v.x * c;
            acc[2 * k + 1] += v.y * c;
        }
    }
    float d = __ldg(&nd[row]);
    uint4 o;
    uint32_t* ow = (uint32_t*)&o;
#pragma unroll
    for (int k = 0; k < 4; k++)
        ow[k] = f22h(acc[2 * k] * d, acc[2 * k + 1] * d);
    *(uint4*)&Out[(size_t)row * DD + lane * 8] = o;
}

// ---------------- fused weight transpose (fp32 -> fp16 transposed, all 4 mats) ----------------
__global__ void transpose_all(const float* __restrict__ W_fc, const float* __restrict__ W1,
                              const float* __restrict__ W2, const float* __restrict__ W3,
                              __half* __restrict__ WT, int F, int D)
{
    int z = blockIdx.z;
    const float* W;
    __half* Wt;
    int K;
    if (z == 0) { W = W_fc; Wt = WT; K = F; }
    else {
        K = D;
        W = (z == 1) ? W1 : (z == 2) ? W2 : W3;
        Wt = WT + (size_t)D * F + (size_t)(z - 1) * D * D;
    }
    int bx = blockIdx.x * 32;  // K dim
    if (bx >= K) return;
    int by = blockIdx.y * 32;  // N dim
    __shared__ float t[32][33];
    int x = threadIdx.x, y = threadIdx.y;
    for (int j = 0; j < 32; j += 8)
        t[y + j][x] = W[(size_t)(bx + y + j) * D + by + x];
    __syncthreads();
    for (int j = 0; j < 32; j += 8)
        Wt[(size_t)(by + y + j) * K + bx + x] = __float2half_rn(t[x][y + j]);
}

// ---------------- fp16 mma GEMM, 128x256 tile, cp.async pipeline (no fused stats) --------
// C[M,256] = A[M,K] @ W + bias; Bt = fp16 W^T [256][K]. Nn fixed = 256.
// 256 threads, 8 warps, warp tile 64x64, acc[4][8][4]; grid (1, ceil(M/128)).
template <bool A_HALF, bool OUT_HALF>
__global__ __launch_bounds__(256, 1) void mma_gemm_t(
    const void* __restrict__ Ap, const __half* __restrict__ Bt,
    const float* __restrict__ bias, void* __restrict__ Cp,
    int M, int K)
{
    __shared__ __align__(16) __half As[2][128 * 32];
    __shared__ __align__(16) __half Bs[2][256 * 32];

    const int tid = threadIdx.x;
    const int lane = tid & 31;
    const int warp = tid >> 5;
    const int wm = warp & 1;    // 64-row half
    const int wn = warp >> 1;   // 64-col quarter
    const int brow = blockIdx.y * 128;
    const int l8 = lane & 7;
    const int q = lane >> 3;

    const float* Af = (const float*)Ap;
    const __half* Ah = (const __half*)Ap;

    const uint32_t asb = smem_u32(&As[0][0]);
    const uint32_t bsb = smem_u32(&Bs[0][0]);

    float acc[4][8][4];
#pragma unroll
    for (int i = 0; i < 4; i++)
#pragma unroll
        for (int j = 0; j < 8; j++)
#pragma unroll
            for (int l = 0; l < 4; l++) acc[i][j][l] = 0.f;

    // load mappings
    int fR[4], fC[4];   // fp32 A: 4 x float4 (register path, needs cvt)
#pragma unroll
    for (int i = 0; i < 4; i++) {
        int idx = tid + i * 256;
        fR[i] = idx >> 3;
        fC[i] = (idx & 7) << 2;
    }
    int hR[2], hC[2];   // fp16 A: 2 x uint4 (cp.async)
#pragma unroll
    for (int i = 0; i < 2; i++) {
        int idx = tid + i * 256;
        hR[i] = idx >> 2;
        hC[i] = (idx & 3) << 3;
    }
    int bR[4], bC[4];   // B: 4 x uint4 over 256 rows (cp.async)
#pragma unroll
    for (int i = 0; i < 4; i++) {
        int idx = tid + i * 256;
        bR[i] = idx >> 2;
        bC[i] = (idx & 3) << 3;
    }

    const int nch = K >> 5;
    float4 ra[4];

    // ---- prologue: chunk 0 into buffer 0
    if (A_HALF) {
#pragma unroll
        for (int i = 0; i < 2; i++) {
            int gr = brow + hR[i];
            cp16z(asb + swoff(hR[i], hC[i]) * 2, &Ah[(size_t)gr * K + hC[i]], gr < M);
        }
    } else {
#pragma unroll
        for (int i = 0; i < 4; i++) {
            int gr = brow + fR[i];
            ra[i] = (gr < M) ? *(const float4*)&Af[(size_t)gr * K + fC[i]]
                             : make_float4(0.f, 0.f, 0.f, 0.f);
        }
#pragma unroll
        for (int i = 0; i < 4; i++)
            *(uint2*)&As[0][swoff(fR[i], fC[i])] =
                make_uint2(f22h(ra[i].x, ra[i].y), f22h(ra[i].z, ra[i].w));
    }
#pragma unroll
    for (int i = 0; i < 4; i++)
        cp16(bsb + swoff(bR[i], bC[i]) * 2, &Bt[(size_t)bR[i] * K + bC[i]]);
    CP_COMMIT();
    CP_WAIT0();
    __syncthreads();

    for (int c = 0; c < nch; c++) {
        const int buf = c & 1;
        const int nb = buf ^ 1;
        const bool more = (c + 1 < nch);
        if (more) {
            int k0 = (c + 1) << 5;
            if (A_HALF) {
#pragma unroll
                for (int i = 0; i < 2; i++) {
                    int gr = brow + hR[i];
                    cp16z(asb + (nb * 4096 + swoff(hR[i], hC[i])) * 2,
                          &Ah[(size_t)gr * K + k0 + hC[i]], gr < M);
                }
            } else {
#pragma unroll
                for (int i = 0; i < 4; i++) {
                    int gr = brow + fR[i];
                    ra[i] = (gr < M) ? *(const float4*)&Af[(size_t)gr * K + k0 + fC[i]]
                                     : make_float4(0.f, 0.f, 0.f, 0.f);
                }
            }
#pragma unroll
            for (int i = 0; i < 4; i++)
                cp16(bsb + (nb * 8192 + swoff(bR[i], bC[i])) * 2,
                     &Bt[(size_t)bR[i] * K + k0 + bC[i]]);
            CP_COMMIT();
        }

        // mma over smem[buf]: two k16 halves
#pragma unroll
        for (int kk = 0; kk < 2; kk++) {
            uint32_t af[4][4], bf[8][2];
#pragma unroll
            for (int mi = 0; mi < 4; mi++) {
                int row = wm * 64 + mi * 16 + ((q & 1) << 3) + l8;
                int col = kk * 16 + ((q >> 1) << 3);
                ldsm4(af[mi], smem_u32(&As[buf][swoff(row, col)]));
            }
#pragma unroll
            for (int p = 0; p < 4; p++) {
                int row = wn * 64 + p * 16 + ((q >> 1) << 3) + l8;
                int col = kk * 16 + ((q & 1) << 3);
                uint32_t r4[4];
                ldsm4(r4, smem_u32(&Bs[buf][swoff(row, col)]));
                bf[2 * p][0] = r4[0]; bf[2 * p][1] = r4[1];
                bf[2 * p + 1][0] = r4[2]; bf[2 * p + 1][1] = r4[3];
            }
#pragma unroll
            for (int mi = 0; mi < 4; mi++)
#pragma unroll
                for (int ni = 0; ni < 8; ni++)
                    mma16816(acc[mi][ni], af[mi], bf[ni]);
        }

        if (more) {
            if (!A_HALF) {
#pragma unroll
                for (int i = 0; i < 4; i++)
                    *(uint2*)&As[nb][swoff(fR[i], fC[i])] =
                        make_uint2(f22h(ra[i].x, ra[i].y), f22h(ra[i].z, ra[i].w));
            }
            CP_WAIT0();
        }
        __syncthreads();
    }

    // epilogue
    float* Cf = (float*)Cp;
    __half* Ch = (__half*)Cp;
#pragma unroll
    for (int mi = 0; mi < 4; mi++) {
        int r0 = brow + wm * 64 + mi * 16 + (lane >> 2);
#pragma unroll
        for (int ni = 0; ni < 8; ni++) {
            int cc = wn * 64 + ni * 8 + (lane & 3) * 2;
            float b0 = bias[cc], b1 = bias[cc + 1];
            if (r0 < M) {
                float v0 = acc[mi][ni][0] + b0, v1 = acc[mi][ni][1] + b1;
                if (OUT_HALF) *(uint32_t*)&Ch[(size_t)r0 * 256 + cc] = f22h(v0, v1);
                else *(float2*)&Cf[(size_t)r0 * 256 + cc] = make_float2(v0, v1);
            }
            if (r0 + 8 < M) {
                float v0 = acc[mi][ni][2] + b0, v1 = acc[mi][ni][3] + b1;
                if (OUT_HALF) *(uint32_t*)&Ch[(size_t)(r0 + 8) * 256 + cc] = f22h(v0, v1);
                else *(float2*)&Cf[(size_t)(r0 + 8) * 256 + cc] = make_float2(v0, v1);
            }
        }
    }
}

// ---------------- batchnorm (fp16 storage, fp32 math, partial-sum arrays) ----------------
__global__ void bn_stats_h(const __half* __restrict__ X, float* __restrict__ psum,
                           float* __restrict__ psq, int Nrows)
{
    int col2 = threadIdx.x;
    int rows_per = (Nrows + gridDim.x - 1) / gridDim.x;
    int r0 = blockIdx.x * rows_per;
    int r1 = min(r0 + rows_per, Nrows);
    float s0 = 0.f, s1 = 0.f, q0 = 0.f, q1 = 0.f;
    const __half2* X2 = (const __half2*)X;
    for (int r = r0; r < r1; r++) {
        float2 v = __half22float2(X2[(size_t)r * (DD / 2) + col2]);
        s0 += v.x; s1 += v.y;
        q0 += v.x * v.x; q1 += v.y * v.y;
    }
    psum[blockIdx.x * DD + col2 * 2 + 0] = s0;
    psum[blockIdx.x * DD + col2 * 2 + 1] = s1;
    psq[blockIdx.x * DD + col2 * 2 + 0] = q0;
    psq[blockIdx.x * DD + col2 * 2 + 1] = q1;
}

__global__ void bn_finalize_kernel(const float* __restrict__ psum, const float* __restrict__ psq,
                                   const float* __restrict__ gamma, const float* __restrict__ beta,
                                   float* __restrict__ scale, float* __restrict__ shift,
                                   int nparts, int Nrows)
{
    int c = threadIdx.x;
    float s = 0.f, q = 0.f;
    for (int r = 0; r < nparts; r++) {
        s += psum[r * DD + c];
        q += psq[r * DD + c];
    }
    float invn = 1.0f / (float)Nrows;
    float mu = s * invn;
    float var = q * invn - mu * mu;
    float inv = rsqrtf(var + 1e-5f);
    float sc = gamma[c] * inv;
    scale[c] = sc;
    shift[c] = beta[c] - mu * sc;
}

__global__ void bn_apply_elu_h(__half* __restrict__ X, const float* __restrict__ scale,
                               const float* __restrict__ shift, long total2)
{
    long t = (long)blockIdx.x * blockDim.x + threadIdx.x;
    if (t >= total2) return;
    int col2 = (int)(t & (DD / 2 - 1));
    __half2* X2 = (__half2*)X;
    float2 v = __half22float2(X2[t]);
    float y0 = v.x * scale[col2 * 2] + shift[col2 * 2];
    float y1 = v.y * scale[col2 * 2 + 1] + shift[col2 * 2 + 1];
    y0 = (y0 > 0.f) ? y0 : expm1f(y0);
    y1 = (y1 > 0.f) ? y1 : expm1f(y1);
    X2[t] = __floats2half2_rn(y0, y1);
}

// ---------------- classifier head ----------------
#define HEAD_ROWS 8
__global__ __launch_bounds__(CC * HEAD_ROWS) void logits_kernel(
    const float* __restrict__ X, const float* __restrict__ W,
    const float* __restrict__ b, float* __restrict__ Out, int Nrows)
{
    __shared__ float Ws[DD * CC];
    for (int i = threadIdx.x; i < DD * CC; i += blockDim.x) Ws[i] = W[i];
    __syncthreads();
    int c = threadIdx.x % CC;
    int rloc = threadIdx.x / CC;
    int row = blockIdx.x * HEAD_ROWS + rloc;
    if (row >= Nrows) return;
    const float* a = &X[(size_t)row * DD];
    float acc = b[c];
#pragma unroll 8
    for (int k = 0; k < DD; k += 4) {
        float4 av = *(const float4*)&a[k];
        acc += av.x * Ws[(k + 0) * CC + c];
        acc += av.y * Ws[(k + 1) * CC + c];
        acc += av.z * Ws[(k + 2) * CC + c];
        acc += av.w * Ws[(k + 3) * CC + c];
    }
    Out[(size_t)row * CC + c] = acc;
}

// ---------------- driver ----------------
extern "C" void kernel_launch(void* const* d_in, const int* in_sizes, int n_in,
                              void* d_out, int out_size)
{
    const float* feat  = (const float*)d_in[0];
    const int*   src   = (const int*)d_in[1];
    const int*   dst   = (const int*)d_in[2];
    const float* W_fc  = (const float*)d_in[3];
    const float* b_fc  = (const float*)d_in[4];
    const float* W1    = (const float*)d_in[5];
    const float* b1    = (const float*)d_in[6];
    const float* W2    = (const float*)d_in[7];
    const float* b2    = (const float*)d_in[8];
    const float* W3    = (const float*)d_in[9];
    const float* b3    = (const float*)d_in[10];
    const float* gamma = (const float*)d_in[11];
    const float* beta  = (const float*)d_in[12];
    const float* W_lin = (const float*)d_in[13];
    const float* b_lin = (const float*)d_in[14];

    const int D = in_sizes[4];             // 256
    const int F = in_sizes[3] / D;         // 1024
    const int N = in_sizes[0] / F;         // 50000
    const int E = in_sizes[1];             // 300000

    float *p_norms, *p_normd, *p_psum, *p_psq, *p_scale, *p_shift;
    int *p_odeg, *p_ideg, *p_offs, *p_cursor, *p_bsum, *p_esrc;
    __half *p_HA, *p_HB, *p_WT;
    cudaGetSymbolAddress((void**)&p_norms, g_norms);
    cudaGetSymbolAddress((void**)&p_normd, g_normd);
    cudaGetSymbolAddress((void**)&p_odeg, g_odeg);
    cudaGetSymbolAddress((void**)&p_ideg, g_ideg);
    cudaGetSymbolAddress((void**)&p_offs, g_offs);
    cudaGetSymbolAddress((void**)&p_cursor, g_cursor);
    cudaGetSymbolAddress((void**)&p_bsum, g_bsum);
    cudaGetSymbolAddress((void**)&p_esrc, g_esrc);
    cudaGetSymbolAddress((void**)&p_HA, g_HA);
    cudaGetSymbolAddress((void**)&p_HB, g_HB);
    cudaGetSymbolAddress((void**)&p_psum, g_psum);
    cudaGetSymbolAddress((void**)&p_psq, g_psq);
    cudaGetSymbolAddress((void**)&p_scale, g_scale);
    cudaGetSymbolAddress((void**)&p_shift, g_shift);
    cudaGetSymbolAddress((void**)&p_WT, g_WT);

    // one-time stream/event setup
    static cudaStream_t s2 = nullptr;
    static cudaEvent_t evFork = nullptr, evJoin = nullptr;
    if (!s2) {
        cudaStreamCreateWithFlags(&s2, cudaStreamNonBlocking);
        cudaEventCreateWithFlags(&evFork, cudaEventDisableTiming);
        cudaEventCreateWithFlags(&evJoin, cudaEventDisableTiming);
    }

    float* out_x = (float*)d_out;                       // [N, D]
    float* out_logits = (float*)d_out + (size_t)N * D;  // [N, C]

    __half* WT_fc = p_WT;
    __half* WT1 = p_WT + (size_t)D * F;
    __half* WT2 = WT1 + (size_t)D * D;
    __half* WT3 = WT2 + (size_t)D * D;

    const int nsb = (N + SCB - 1) / SCB;
    const int mblocks = (N + 127) / 128;

    // ---- fork: CSR/degree chain on s2, overlapped with transpose + FC GEMM
    cudaEventRecord(evFork, 0);
    cudaStreamWaitEvent(s2, evFork, 0);

    cudaMemsetAsync(p_odeg, 0, N * sizeof(int), s2);
    cudaMemsetAsync(p_ideg, 0, N * sizeof(int), s2);
    deg_kernel<<<(E + 255) / 256, 256, 0, s2>>>(src, dst, p_odeg, p_ideg, E);
    norm_kernel<<<(N + 255) / 256, 256, 0, s2>>>(p_odeg, p_ideg, p_norms, p_normd, N);
    scan_part<<<nsb, SCB, 0, s2>>>(p_ideg, p_bsum, N);
    scan_base<<<1, 256, 0, s2>>>(p_bsum, nsb);
    scan_final<<<nsb, SCB, 0, s2>>>(p_ideg, p_bsum, p_offs, p_cursor, N);
    fill_kernel<<<(E + 255) / 256, 256, 0, s2>>>(src, dst, p_cursor, p_esrc, E);
    cudaEventRecord(evJoin, s2);

    // ---- main stream: weights + FC GEMM
    {
        dim3 blk(32, 8);
        dim3 grid(F / 32, D / 32, 4);
        transpose_all<<<grid, blk>>>(W_fc, W1, W2, W3, p_WT, F, D);
    }
    dim3 ggrid(1, mblocks);
    mma_gemm_t<false, true><<<ggrid, 256>>>(feat, WT_fc, b_fc, p_HA, N, F);

    // ---- join before first spmm
    cudaStreamWaitEvent(0, evJoin, 0);

    const __half* WTs[3] = {WT1, WT2, WT3};
    const float* bs[3] = {b1, b2, b3};
    long total2 = (long)N * D / 2;

    for (int l = 0; l < 3; l++) {
        spmm_gather_h<<<(N + 7) / 8, 256>>>(p_HA, p_esrc, p_offs, p_norms, p_normd, p_HB, N);
        if (l < 2) {
            mma_gemm_t<true, true><<<ggrid, 256>>>(p_HB, WTs[l], bs[l], p_HA, N, D);
            bn_stats_h<<<512, D / 2>>>(p_HA, p_psum, p_psq, N);
            bn_finalize_kernel<<<1, D>>>(p_psum, p_psq, gamma, beta, p_scale, p_shift, 512, N);
            bn_apply_elu_h<<<(int)((total2 + 255) / 256), 256>>>(p_HA, p_scale, p_shift, total2);
        } else {
            mma_gemm_t<true, false><<<ggrid, 256>>>(p_HB, WTs[l], bs[l], out_x, N, D);
        }
    }

    // 3. logits
    logits_kernel<<<(N + HEAD_ROWS - 1) / HEAD_ROWS, CC * HEAD_ROWS>>>(
        out_x, W_lin, b_lin, out_logits, N);
}

// round 12
// speedup vs baseline: 1.5014x; 1.3129x over previous
#include <cuda_runtime.h>
#include <cuda_fp16.h>
#include <math.h>
#include <stdint.h>

#define NN 50000
#define EE 300000
#define DD 256
#define FF 1024
#define CC 40

// ---------------- scratch (device globals) ----------------
__device__ float g_norms[NN];
__device__ float g_normd[NN];
__device__ int   g_odeg[NN];
__device__ int   g_ideg[NN];
__device__ int   g_offs[NN + 1];
__device__ int   g_cursor[NN];
__device__ int   g_bsum[256];
__device__ int   g_esrc[EE];
__device__ __half g_HA[(size_t)NN * DD];   // fp16 activations
__device__ __half g_HB[(size_t)NN * DD];   // fp16 spmm output
__device__ float g_psum[512 * DD];         // bn partial sums
__device__ float g_psq[512 * DD];
__device__ float g_scale[DD];
__device__ float g_shift[DD];
// fp16 transposed weights: WT_fc [256][1024], WT1/2/3 [256][256], WLT [64][256]
__device__ __half g_WT[(size_t)DD * FF + 3 * (size_t)DD * DD + 64 * DD];

// ---------------- helpers ----------------
__device__ __forceinline__ uint32_t smem_u32(const void* p) {
    uint32_t a;
    asm("{ .reg .u64 t; cvta.to.shared.u64 t, %1; cvt.u32.u64 %0, t; }" : "=r"(a) : "l"(p));
    return a;
}
__device__ __forceinline__ uint32_t f22h(float a, float b) {
    __half2 h = __float22half2_rn(make_float2(a, b));
    return *(uint32_t*)&h;
}
__device__ __forceinline__ void ldsm4(uint32_t* r, uint32_t addr) {
    asm volatile("ldmatrix.sync.aligned.m8n8.x4.shared.b16 {%0,%1,%2,%3}, [%4];"
                 : "=r"(r[0]), "=r"(r[1]), "=r"(r[2]), "=r"(r[3]) : "r"(addr));
}
__device__ __forceinline__ void mma16816(float* c, const uint32_t* a, const uint32_t* b) {
    asm volatile(
        "mma.sync.aligned.m16n8k16.row.col.f32.f16.f16.f32 "
        "{%0,%1,%2,%3}, {%4,%5,%6,%7}, {%8,%9}, {%0,%1,%2,%3};"
        : "+f"(c[0]), "+f"(c[1]), "+f"(c[2]), "+f"(c[3])
        : "r"(a[0]), "r"(a[1]), "r"(a[2]), "r"(a[3]), "r"(b[0]), "r"(b[1]));
}
__device__ __forceinline__ void cp16(uint32_t dst, const void* src) {
    asm volatile("cp.async.cg.shared.global [%0], [%1], 16;" :: "r"(dst), "l"(src));
}
__device__ __forceinline__ void cp16z(uint32_t dst, const void* src, bool valid) {
    int sz = valid ? 16 : 0;
    asm volatile("cp.async.cg.shared.global [%0], [%1], 16, %2;"
                 :: "r"(dst), "l"(src), "r"(sz));
}
#define CP_COMMIT() asm volatile("cp.async.commit_group;" ::: "memory")
#define CP_WAIT0()  asm volatile("cp.async.wait_group 0;" ::: "memory")

// swizzled half offset within a [rows][32] half tile (64B rows, 4x16B groups)
__device__ __forceinline__ int swoff(int r, int c) {
    return r * 32 + ((((c >> 3) ^ ((r >> 1) & 3)) << 3)) + (c & 7);
}

// ---------------- degree + norm ----------------
__global__ void deg_kernel(const int* __restrict__ src, const int* __restrict__ dst,
                           int* __restrict__ od, int* __restrict__ id, int E) {
    int t = blockIdx.x * blockDim.x + threadIdx.x;
    if (t >= E) return;
    atomicAdd(&od[src[t]], 1);
    atomicAdd(&id[dst[t]], 1);
}

__global__ void norm_kernel(const int* __restrict__ od, const int* __restrict__ id,
                            float* __restrict__ ns, float* __restrict__ nd, int n) {
    int t = blockIdx.x * blockDim.x + threadIdx.x;
    if (t >= n) return;
    ns[t] = rsqrtf(fmaxf((float)od[t], 1.0f));
    nd[t] = rsqrtf(fmaxf((float)id[t], 1.0f));
}

// ---------------- CSR build: 3-phase multi-block scan ----------------
#define SCB 256
__global__ void scan_part(const int* __restrict__ deg, int* __restrict__ bsum, int n) {
    __shared__ int sh[SCB];
    int t = threadIdx.x;
    int i = blockIdx.x * SCB + t;
    sh[t] = (i < n) ? deg[i] : 0;
    __syncthreads();
#pragma unroll
    for (int o = 128; o > 0; o >>= 1) {
        if (t < o) sh[t] += sh[t + o];
        __syncthreads();
    }
    if (t == 0) bsum[blockIdx.x] = sh[0];
}

__global__ void scan_base(int* __restrict__ bsum, int nb) {
    __shared__ int sh[256];
    int t = threadIdx.x;
    int v = (t < nb) ? bsum[t] : 0;
    sh[t] = v;
    __syncthreads();
#pragma unroll
    for (int o = 1; o < 256; o <<= 1) {
        int u = (t >= o) ? sh[t - o] : 0;
        __syncthreads();
        sh[t] += u;
        __syncthreads();
    }
    if (t < nb) bsum[t] = sh[t] - v;   // exclusive
}

__global__ void scan_final(const int* __restrict__ deg, const int* __restrict__ bsum,
                           int* __restrict__ offs, int* __restrict__ cursor, int n) {
    __shared__ int sh[SCB];
    int t = threadIdx.x;
    int i = blockIdx.x * SCB + t;
    int v = (i < n) ? deg[i] : 0;
    sh[t] = v;
    __syncthreads();
#pragma unroll
    for (int o = 1; o < SCB; o <<= 1) {
        int u = (t >= o) ? sh[t - o] : 0;
        __syncthreads();
        sh[t] += u;
        __syncthreads();
    }
    int excl = sh[t] - v + bsum[blockIdx.x];
    if (i < n) {
        offs[i] = excl;
        cursor[i] = excl;
        if (i == n - 1) offs[n] = excl + v;
    }
}

__global__ void fill_kernel(const int* __restrict__ src, const int* __restrict__ dst,
                            int* __restrict__ cursor, int* __restrict__ esrc, int E) {
    int e = blockIdx.x * blockDim.x + threadIdx.x;
    if (e >= E) return;
    int p = atomicAdd(&cursor[dst[e]], 1);
    esrc[p] = src[e];
}

// ---------------- SpMM gather (fp16 in/out, fp32 accum, norm_d folded in) ----------------
__global__ __launch_bounds__(256) void spmm_gather_h(
    const __half* __restrict__ X, const int* __restrict__ esrc,
    const int* __restrict__ offs, const float* __restrict__ ns,
    const float* __restrict__ nd, __half* __restrict__ Out, int n)
{
    int row = blockIdx.x * 8 + (threadIdx.x >> 5);
    int lane = threadIdx.x & 31;
    if (row >= n) return;
    int o0 = offs[row], o1 = offs[row + 1];
    float acc[8];
#pragma unroll
    for (int k = 0; k < 8; k++) acc[k] = 0.f;

    int i = o0;
    for (; i + 4 <= o1; i += 4) {
        int s[4];
        float c[4];
        uint4 u[4];
#pragma unroll
        for (int j = 0; j < 4; j++) s[j] = __ldg(&esrc[i + j]);
#pragma unroll
        for (int j = 0; j < 4; j++) {
            c[j] = __ldg(&ns[s[j]]);
            u[j] = *(const uint4*)&X[(size_t)s[j] * DD + lane * 8];
        }
#pragma unroll
        for (int j = 0; j < 4; j++) {
            const __half2* h = (const __half2*)&u[j];
#pragma unroll
            for (int k = 0; k < 4; k++) {
                float2 v = __half22float2(h[k]);
                acc[2 * k] += v.x * c[j];
                acc[2 * k + 1] += v.y * c[j];
            }
        }
    }
    for (; i < o1; i++) {
        int s = __ldg(&esrc[i]);
        float c = __ldg(&ns[s]);
        uint4 u = *(const uint4*)&X[(size_t)s * DD + lane * 8];
        const __half2* h = (const __half2*)&u;
#pragma unroll
        for (int k = 0; k < 4; k++) {
            float2 v = __half22float2(h[k]);
            acc[2 * k] += v.x * c;
            acc[2 * k + 1] += v.y * c;
        }
    }
    float d = __ldg(&nd[row]);
    uint4 o;
    uint32_t* ow = (uint32_t*)&o;
#pragma unroll
    for (int k = 0; k < 4; k++)
        ow[k] = f22h(acc[2 * k] * d, acc[2 * k + 1] * d);
    *(uint4*)&Out[(size_t)row * DD + lane * 8] = o;
}

// ---------------- fused weight transpose (fp32 -> fp16 transposed, 5 slices) ----------------
// z=0: W_fc [1024][256] -> WT [256][1024]
// z=1..3: W1/2/3 [256][256] -> WT1/2/3 [256][256]
// z=4: W_lin [256][40] -> WLT [64][256] (zero-padded cols 40..63)
__global__ void transpose_all(const float* __restrict__ W_fc, const float* __restrict__ W1,
                              const float* __restrict__ W2, const float* __restrict__ W3,
                              const float* __restrict__ W_lin,
                              __half* __restrict__ WT, int F, int D)
{
    int z = blockIdx.z;
    __shared__ float t[32][33];
    int x = threadIdx.x, y = threadIdx.y;
    int bx = blockIdx.x * 32;  // K dim (rows of src)
    int by = blockIdx.y * 32;  // N dim (cols of src)

    if (z == 4) {
        if (bx >= D || by >= 64) return;
        __half* WLT = WT + (size_t)D * F + 3 * (size_t)D * D;
        for (int j = 0; j < 32; j += 8)
            t[y + j][x] = (by + x < CC) ? W_lin[(size_t)(bx + y + j) * CC + by + x] : 0.f;
        __syncthreads();
        for (int j = 0; j < 32; j += 8)
            WLT[(size_t)(by + y + j) * D + bx + x] = __float2half_rn(t[x][y + j]);
        return;
    }

    const float* W;
    __half* Wt;
    int K;
    if (z == 0) { W = W_fc; Wt = WT; K = F; }
    else {
        K = D;
        W = (z == 1) ? W1 : (z == 2) ? W2 : W3;
        Wt = WT + (size_t)D * F + (size_t)(z - 1) * D * D;
    }
    if (bx >= K) return;
    for (int j = 0; j < 32; j += 8)
        t[y + j][x] = W[(size_t)(bx + y + j) * D + by + x];
    __syncthreads();
    for (int j = 0; j < 32; j += 8)
        Wt[(size_t)(by + y + j) * K + bx + x] = __float2half_rn(t[x][y + j]);
}

// ---------------- fp16 mma GEMM, 128x256 tile, cp.async pipeline ----------------
// C[M,256] = A[M,K] @ W + bias; Bt = fp16 W^T [256][K]. Nn fixed = 256.
// 256 threads, 8 warps, warp tile 64x64, acc[4][8][4]; grid (1, ceil(M/128)).
// C2 (optional, fp32-out path only): also write an fp16 copy.
template <bool A_HALF, bool OUT_HALF>
__global__ __launch_bounds__(256, 1) void mma_gemm_t(
    const void* __restrict__ Ap, const __half* __restrict__ Bt,
    const float* __restrict__ bias, void* __restrict__ Cp,
    __half* __restrict__ C2, int M, int K)
{
    __shared__ __align__(16) __half As[2][128 * 32];
    __shared__ __align__(16) __half Bs[2][256 * 32];

    const int tid = threadIdx.x;
    const int lane = tid & 31;
    const int warp = tid >> 5;
    const int wm = warp & 1;    // 64-row half
    const int wn = warp >> 1;   // 64-col quarter
    const int brow = blockIdx.y * 128;
    const int l8 = lane & 7;
    const int q = lane >> 3;

    const float* Af = (const float*)Ap;
    const __half* Ah = (const __half*)Ap;

    const uint32_t asb = smem_u32(&As[0][0]);
    const uint32_t bsb = smem_u32(&Bs[0][0]);

    float acc[4][8][4];
#pragma unroll
    for (int i = 0; i < 4; i++)
#pragma unroll
        for (int j = 0; j < 8; j++)
#pragma unroll
            for (int l = 0; l < 4; l++) acc[i][j][l] = 0.f;

    // load mappings
    int fR[4], fC[4];   // fp32 A: 4 x float4 (register path, needs cvt)
#pragma unroll
    for (int i = 0; i < 4; i++) {
        int idx = tid + i * 256;
        fR[i] = idx >> 3;
        fC[i] = (idx & 7) << 2;
    }
    int hR[2], hC[2];   // fp16 A: 2 x uint4 (cp.async)
#pragma unroll
    for (int i = 0; i < 2; i++) {
        int idx = tid + i * 256;
        hR[i] = idx >> 2;
        hC[i] = (idx & 3) << 3;
    }
    int bR[4], bC[4];   // B: 4 x uint4 over 256 rows (cp.async)
#pragma unroll
    for (int i = 0; i < 4; i++) {
        int idx = tid + i * 256;
        bR[i] = idx >> 2;
        bC[i] = (idx & 3) << 3;
    }

    const int nch = K >> 5;
    float4 ra[4];

    // ---- prologue: chunk 0 into buffer 0
    if (A_HALF) {
#pragma unroll
        for (int i = 0; i < 2; i++) {
            int gr = brow + hR[i];
            cp16z(asb + swoff(hR[i], hC[i]) * 2, &Ah[(size_t)gr * K + hC[i]], gr < M);
        }
    } else {
#pragma unroll
        for (int i = 0; i < 4; i++) {
            int gr = brow + fR[i];
            ra[i] = (gr < M) ? *(const float4*)&Af[(size_t)gr * K + fC[i]]
                             : make_float4(0.f, 0.f, 0.f, 0.f);
        }
#pragma unroll
        for (int i = 0; i < 4; i++)
            *(uint2*)&As[0][swoff(fR[i], fC[i])] =
                make_uint2(f22h(ra[i].x, ra[i].y), f22h(ra[i].z, ra[i].w));
    }
#pragma unroll
    for (int i = 0; i < 4; i++)
        cp16(bsb + swoff(bR[i], bC[i]) * 2, &Bt[(size_t)bR[i] * K + bC[i]]);
    CP_COMMIT();
    CP_WAIT0();
    __syncthreads();

    for (int c = 0; c < nch; c++) {
        const int buf = c & 1;
        const int nb = buf ^ 1;
        const bool more = (c + 1 < nch);
        if (more) {
            int k0 = (c + 1) << 5;
            if (A_HALF) {
#pragma unroll
                for (int i = 0; i < 2; i++) {
                    int gr = brow + hR[i];
                    cp16z(asb + (nb * 4096 + swoff(hR[i], hC[i])) * 2,
                          &Ah[(size_t)gr * K + k0 + hC[i]], gr < M);
                }
            } else {
#pragma unroll
                for (int i = 0; i < 4; i++) {
                    int gr = brow + fR[i];
                    ra[i] = (gr < M) ? *(const float4*)&Af[(size_t)gr * K + k0 + fC[i]]
                                     : make_float4(0.f, 0.f, 0.f, 0.f);
                }
            }
#pragma unroll
            for (int i = 0; i < 4; i++)
                cp16(bsb + (nb * 8192 + swoff(bR[i], bC[i])) * 2,
                     &Bt[(size_t)bR[i] * K + k0 + bC[i]]);
            CP_COMMIT();
        }

        // mma over smem[buf]: two k16 halves
#pragma unroll
        for (int kk = 0; kk < 2; kk++) {
            uint32_t af[4][4], bf[8][2];
#pragma unroll
            for (int mi = 0; mi < 4; mi++) {
                int row = wm * 64 + mi * 16 + ((q & 1) << 3) + l8;
                int col = kk * 16 + ((q >> 1) << 3);
                ldsm4(af[mi], smem_u32(&As[buf][swoff(row, col)]));
            }
#pragma unroll
            for (int p = 0; p < 4; p++) {
                int row = wn * 64 + p * 16 + ((q >> 1) << 3) + l8;
                int col = kk * 16 + ((q & 1) << 3);
                uint32_t r4[4];
                ldsm4(r4, smem_u32(&Bs[buf][swoff(row, col)]));
                bf[2 * p][0] = r4[0]; bf[2 * p][1] = r4[1];
                bf[2 * p + 1][0] = r4[2]; bf[2 * p + 1][1] = r4[3];
            }
#pragma unroll
            for (int mi = 0; mi < 4; mi++)
#pragma unroll
                for (int ni = 0; ni < 8; ni++)
                    mma16816(acc[mi][ni], af[mi], bf[ni]);
        }

        if (more) {
            if (!A_HALF) {
#pragma unroll
                for (int i = 0; i < 4; i++)
                    *(uint2*)&As[nb][swoff(fR[i], fC[i])] =
                        make_uint2(f22h(ra[i].x, ra[i].y), f22h(ra[i].z, ra[i].w));
            }
            CP_WAIT0();
        }
        __syncthreads();
    }

    // epilogue
    float* Cf = (float*)Cp;
    __half* Ch = (__half*)Cp;
#pragma unroll
    for (int mi = 0; mi < 4; mi++) {
        int r0 = brow + wm * 64 + mi * 16 + (lane >> 2);
#pragma unroll
        for (int ni = 0; ni < 8; ni++) {
            int cc = wn * 64 + ni * 8 + (lane & 3) * 2;
            float b0 = bias[cc], b1 = bias[cc + 1];
            if (r0 < M) {
                float v0 = acc[mi][ni][0] + b0, v1 = acc[mi][ni][1] + b1;
                if (OUT_HALF) *(uint32_t*)&Ch[(size_t)r0 * 256 + cc] = f22h(v0, v1);
                else {
                    *(float2*)&Cf[(size_t)r0 * 256 + cc] = make_float2(v0, v1);
                    if (C2) *(uint32_t*)&C2[(size_t)r0 * 256 + cc] = f22h(v0, v1);
                }
            }
            if (r0 + 8 < M) {
                float v0 = acc[mi][ni][2] + b0, v1 = acc[mi][ni][3] + b1;
                if (OUT_HALF) *(uint32_t*)&Ch[(size_t)(r0 + 8) * 256 + cc] = f22h(v0, v1);
                else {
                    *(float2*)&Cf[(size_t)(r0 + 8) * 256 + cc] = make_float2(v0, v1);
                    if (C2) *(uint32_t*)&C2[(size_t)(r0 + 8) * 256 + cc] = f22h(v0, v1);
                }
            }
        }
    }
}

// ---------------- head GEMM: Out[M,40] = A[M,256](fp16) @ WLT^T + bias ----------------
// WLT: fp16 [64][256] (N-major, zero-padded). Tile 128x64, B fully smem-resident.
__global__ __launch_bounds__(256) void head_mma(
    const __half* __restrict__ A, const __half* __restrict__ Bt,
    const float* __restrict__ bias, float* __restrict__ Out, int M)
{
    __shared__ __align__(16) __half As[2][128 * 32];  // 16 KB
    __shared__ __align__(16) __half Bs[8 * 2048];     // 32 KB: 8 chunks of [64][32]

    const int tid = threadIdx.x;
    const int lane = tid & 31;
    const int warp = tid >> 5;
    const int wm = warp & 1;    // 64-row half
    const int wn = warp >> 1;   // 16-col group (0..3)
    const int brow = blockIdx.y * 128;
    const int l8 = lane & 7;
    const int q = lane >> 3;

    const uint32_t asb = smem_u32(&As[0][0]);
    const uint32_t bsb = smem_u32(&Bs[0]);

    float acc[4][2][4];
#pragma unroll
    for (int i = 0; i < 4; i++)
#pragma unroll
        for (int j = 0; j < 2; j++)
#pragma unroll
            for (int l = 0; l < 4; l++) acc[i][j][l] = 0.f;

    // A load mapping: 2 x uint4 per thread covers 128 rows x 32 halves
    int hR[2], hC[2];
#pragma unroll
    for (int i = 0; i < 2; i++) {
        int idx = tid + i * 256;
        hR[i] = idx >> 2;          // 0..127
        hC[i] = (idx & 3) << 3;    // 0,8,16,24
    }

    // load full B (64x256 halves) into 8 chunk tiles
#pragma unroll
    for (int i = 0; i < 8; i++) {
        int idx = tid + i * 256;   // 0..2047
        int row = idx >> 5;        // 0..63
        int col = (idx & 31) << 3; // 0..248
        int ch = col >> 5;
        int c32 = col & 31;
        cp16(bsb + (ch * 2048 + swoff(row, c32)) * 2, &Bt[(size_t)row * 256 + col]);
    }
    // A chunk 0 (both halves)
#pragma unroll
    for (int i = 0; i < 2; i++) {
        int gr = brow + hR[i];
        cp16z(asb + swoff(hR[i], hC[i]) * 2, &A[(size_t)gr * 256 + hC[i]], gr < M);
    }
    CP_COMMIT();
    CP_WAIT0();
    __syncthreads();

    for (int c = 0; c < 8; c++) {
        const int buf = c & 1;
        const int nb = buf ^ 1;
        const bool more = (c + 1 < 8);
        if (more) {
            int k0 = (c + 1) << 5;
#pragma unroll
            for (int i = 0; i < 2; i++) {
                int gr = brow + hR[i];
                cp16z(asb + (nb * 4096 + swoff(hR[i], hC[i])) * 2,
                      &A[(size_t)gr * 256 + k0 + hC[i]], gr < M);
            }
            CP_COMMIT();
        }
#pragma unroll
        for (int kk = 0; kk < 2; kk++) {
            uint32_t af[4][4], bf[2][2];
            {
                int row = wn * 16 + ((q >> 1) << 3) + l8;
                int col = kk * 16 + ((q & 1) << 3);
                uint32_t r4[4];
                ldsm4(r4, smem_u32(&Bs[c * 2048 + swoff(row, col)]));
                bf[0][0] = r4[0]; bf[0][1] = r4[1];
                bf[1][0] = r4[2]; bf[1][1] = r4[3];
            }
#pragma unroll
            for (int mi = 0; mi < 4; mi++) {
                int row = wm * 64 + mi * 16 + ((q & 1) << 3) + l8;
                int col = kk * 16 + ((q >> 1) << 3);
                ldsm4(af[mi], smem_u32(&As[buf][swoff(row, col)]));
            }
#pragma unroll
            for (int mi = 0; mi < 4; mi++)
#pragma unroll
                for (int ni = 0; ni < 2; ni++)
                    mma16816(acc[mi][ni], af[mi], bf[ni]);
        }
        if (more) CP_WAIT0();
        __syncthreads();
    }

    // epilogue: write only cols < 40
#pragma unroll
    for (int mi = 0; mi < 4; mi++) {
        int r0 = brow + wm * 64 + mi * 16 + (lane >> 2);
#pragma unroll
        for (int ni = 0; ni < 2; ni++) {
            int cc = wn * 16 + ni * 8 + (lane & 3) * 2;
            if (cc < CC) {
                float b0 = bias[cc], b1 = bias[cc + 1];
                if (r0 < M)
                    *(float2*)&Out[(size_t)r0 * CC + cc] =
                        make_float2(acc[mi][ni][0] + b0, acc[mi][ni][1] + b1);
                if (r0 + 8 < M)
                    *(float2*)&Out[(size_t)(r0 + 8) * CC + cc] =
                        make_float2(acc[mi][ni][2] + b0, acc[mi][ni][3] + b1);
            }
        }
    }
}

// ---------------- batchnorm (fp16 storage, fp32 math, partial-sum arrays) ----------------
__global__ void bn_stats_h(const __half* __restrict__ X, float* __restrict__ psum,
                           float* __restrict__ psq, int Nrows)
{
    int col2 = threadIdx.x;
    int rows_per = (Nrows + gridDim.x - 1) / gridDim.x;
    int r0 = blockIdx.x * rows_per;
    int r1 = min(r0 + rows_per, Nrows);
    float s0 = 0.f, s1 = 0.f, q0 = 0.f, q1 = 0.f;
    const __half2* X2 = (const __half2*)X;
    for (int r = r0; r < r1; r++) {
        float2 v = __half22float2(X2[(size_t)r * (DD / 2) + col2]);
        s0 += v.x; s1 += v.y;
        q0 += v.x * v.x; q1 += v.y * v.y;
    }
    psum[blockIdx.x * DD + col2 * 2 + 0] = s0;
    psum[blockIdx.x * DD + col2 * 2 + 1] = s1;
    psq[blockIdx.x * DD + col2 * 2 + 0] = q0;
    psq[blockIdx.x * DD + col2 * 2 + 1] = q1;
}

__global__ void bn_finalize_kernel(const float* __restrict__ psum, const float* __restrict__ psq,
                                   const float* __restrict__ gamma, const float* __restrict__ beta,
                                   float* __restrict__ scale, float* __restrict__ shift,
                                   int nparts, int Nrows)
{
    int c = threadIdx.x;
    float s = 0.f, q = 0.f;
    for (int r = 0; r < nparts; r++) {
        s += psum[r * DD + c];
        q += psq[r * DD + c];
    }
    float invn = 1.0f / (float)Nrows;
    float mu = s * invn;
    float var = q * invn - mu * mu;
    float inv = rsqrtf(var + 1e-5f);
    float sc = gamma[c] * inv;
    scale[c] = sc;
    shift[c] = beta[c] - mu * sc;
}

__global__ void bn_apply_elu_h(__half* __restrict__ X, const float* __restrict__ scale,
                               const float* __restrict__ shift, long total8)
{
    long t = (long)blockIdx.x * blockDim.x + threadIdx.x;
    if (t >= total8) return;
    int col8 = (int)(t & (DD / 8 - 1));
    uint4 u = ((uint4*)X)[t];
    __half2* h = (__half2*)&u;
#pragma unroll
    for (int k = 0; k < 4; k++) {
        int c = col8 * 8 + k * 2;
        float2 v = __half22float2(h[k]);
        float y0 = v.x * scale[c] + shift[c];
        float y1 = v.y * scale[c + 1] + shift[c + 1];
        y0 = (y0 > 0.f) ? y0 : expm1f(y0);
        y1 = (y1 > 0.f) ? y1 : expm1f(y1);
        h[k] = __floats2half2_rn(y0, y1);
    }
    ((uint4*)X)[t] = u;
}

// ---------------- driver ----------------
extern "C" void kernel_launch(void* const* d_in, const int* in_sizes, int n_in,
                              void* d_out, int out_size)
{
    const float* feat  = (const float*)d_in[0];
    const int*   src   = (const int*)d_in[1];
    const int*   dst   = (const int*)d_in[2];
    const float* W_fc  = (const float*)d_in[3];
    const float* b_fc  = (const float*)d_in[4];
    const float* W1    = (const float*)d_in[5];
    const float* b1    = (const float*)d_in[6];
    const float* W2    = (const float*)d_in[7];
    const float* b2    = (const float*)d_in[8];
    const float* W3    = (const float*)d_in[9];
    const float* b3    = (const float*)d_in[10];
    const float* gamma = (const float*)d_in[11];
    const float* beta  = (const float*)d_in[12];
    const float* W_lin = (const float*)d_in[13];
    const float* b_lin = (const float*)d_in[14];

    const int D = in_sizes[4];             // 256
    const int F = in_sizes[3] / D;         // 1024
    const int N = in_sizes[0] / F;         // 50000
    const int E = in_sizes[1];             // 300000

    float *p_norms, *p_normd, *p_psum, *p_psq, *p_scale, *p_shift;
    int *p_odeg, *p_ideg, *p_offs, *p_cursor, *p_bsum, *p_esrc;
    __half *p_HA, *p_HB, *p_WT;
    cudaGetSymbolAddress((void**)&p_norms, g_norms);
    cudaGetSymbolAddress((void**)&p_normd, g_normd);
    cudaGetSymbolAddress((void**)&p_odeg, g_odeg);
    cudaGetSymbolAddress((void**)&p_ideg, g_ideg);
    cudaGetSymbolAddress((void**)&p_offs, g_offs);
    cudaGetSymbolAddress((void**)&p_cursor, g_cursor);
    cudaGetSymbolAddress((void**)&p_bsum, g_bsum);
    cudaGetSymbolAddress((void**)&p_esrc, g_esrc);
    cudaGetSymbolAddress((void**)&p_HA, g_HA);
    cudaGetSymbolAddress((void**)&p_HB, g_HB);
    cudaGetSymbolAddress((void**)&p_psum, g_psum);
    cudaGetSymbolAddress((void**)&p_psq, g_psq);
    cudaGetSymbolAddress((void**)&p_scale, g_scale);
    cudaGetSymbolAddress((void**)&p_shift, g_shift);
    cudaGetSymbolAddress((void**)&p_WT, g_WT);

    // one-time stream/event setup
    static cudaStream_t s2 = nullptr;
    static cudaEvent_t evFork = nullptr, evJoin = nullptr;
    if (!s2) {
        cudaStreamCreateWithFlags(&s2, cudaStreamNonBlocking);
        cudaEventCreateWithFlags(&evFork, cudaEventDisableTiming);
        cudaEventCreateWithFlags(&evJoin, cudaEventDisableTiming);
    }

    float* out_x = (float*)d_out;                       // [N, D]
    float* out_logits = (float*)d_out + (size_t)N * D;  // [N, C]

    __half* WT_fc = p_WT;
    __half* WT1 = p_WT + (size_t)D * F;
    __half* WT2 = WT1 + (size_t)D * D;
    __half* WT3 = WT2 + (size_t)D * D;
    __half* WLT = WT3 + (size_t)D * D;      // [64][256]

    const int nsb = (N + SCB - 1) / SCB;
    const int mblocks = (N + 127) / 128;

    // ---- fork: CSR/degree chain on s2, overlapped with transpose + FC GEMM
    cudaEventRecord(evFork, 0);
    cudaStreamWaitEvent(s2, evFork, 0);

    cudaMemsetAsync(p_odeg, 0, N * sizeof(int), s2);
    cudaMemsetAsync(p_ideg, 0, N * sizeof(int), s2);
    deg_kernel<<<(E + 255) / 256, 256, 0, s2>>>(src, dst, p_odeg, p_ideg, E);
    norm_kernel<<<(N + 255) / 256, 256, 0, s2>>>(p_odeg, p_ideg, p_norms, p_normd, N);
    scan_part<<<nsb, SCB, 0, s2>>>(p_ideg, p_bsum, N);
    scan_base<<<1, 256, 0, s2>>>(p_bsum, nsb);
    scan_final<<<nsb, SCB, 0, s2>>>(p_ideg, p_bsum, p_offs, p_cursor, N);
    fill_kernel<<<(E + 255) / 256, 256, 0, s2>>>(src, dst, p_cursor, p_esrc, E);
    cudaEventRecord(evJoin, s2);

    // ---- main stream: weights + FC GEMM
    {
        dim3 blk(32, 8);
        dim3 grid(F / 32, D / 32, 5);
        transpose_all<<<grid, blk>>>(W_fc, W1, W2, W3, W_lin, p_WT, F, D);
    }
    dim3 ggrid(1, mblocks);
    mma_gemm_t<false, true><<<ggrid, 256>>>(feat, WT_fc, b_fc, p_HA, nullptr, N, F);

    // ---- join before first spmm
    cudaStreamWaitEvent(0, evJoin, 0);

    const __half* WTs[3] = {WT1, WT2, WT3};
    const float* bs[3] = {b1, b2, b3};
    long total8 = (long)N * D / 8;

    for (int l = 0; l < 3; l++) {
        spmm_gather_h<<<(N + 7) / 8, 256>>>(p_HA, p_esrc, p_offs, p_norms, p_normd, p_HB, N);
        if (l < 2) {
            mma_gemm_t<true, true><<<ggrid, 256>>>(p_HB, WTs[l], bs[l], p_HA, nullptr, N, D);
            bn_stats_h<<<512, D / 2>>>(p_HA, p_psum, p_psq, N);
            bn_finalize_kernel<<<1, D>>>(p_psum, p_psq, gamma, beta, p_scale, p_shift, 512, N);
            bn_apply_elu_h<<<(int)((total8 + 255) / 256), 256>>>(p_HA, p_scale, p_shift, total8);
        } else {
            // layer 3: write fp32 out_x + fp16 copy for the head GEMM
            mma_gemm_t<true, false><<<ggrid, 256>>>(p_HB, WTs[l], bs[l], out_x, p_HA, N, D);
        }
    }

    // 3. logits via tensor cores
    head_mma<<<dim3(1, mblocks), 256>>>(p_HA, WLT, b_lin, out_logits, N);
}